// round 3
// baseline (speedup 1.0000x reference)
#include <cuda_runtime.h>
#include <math.h>

#define NN      10000
#define NG      64
#define ET      330000   // E0 + self loops

// ---------------- device scratch (static; no allocation) ----------------
__device__ float g_xl1[NN * 1024];   // x @ W1          [N, 8*128]
__device__ float g_h1 [NN * 1024];   // layer1 output   [N, 1024]
__device__ float g_as1[NN * 8];
__device__ float g_ad1[NN * 8];
__device__ float g_xl2[NN * 128];    // h1 @ W2         [N, 128]
__device__ float g_as2[NN];
__device__ float g_ad2[NN];
__device__ float g_h2 [NN * 128];    // layer2 output
__device__ float g_pooled[NG * 128];
__device__ int   g_cnt[NN];
__device__ int   g_cur[NN];
__device__ int   g_off[NN + 1];
__device__ int   g_csr_src[ET];

// ---------------- helpers ----------------
// edge_index / batch are INT32 (JAX x64-disabled downcasts jnp.int64 -> int32).
__device__ __forceinline__ void get_edge(const int* ei, int E0, int e,
                                         int& s, int& d) {
    if (e < E0) { s = ei[e]; d = ei[E0 + e]; }
    else        { s = e - E0; d = e - E0; }
}

__device__ __forceinline__ float lrelu(float x) { return x > 0.f ? x : 0.2f * x; }
__device__ __forceinline__ float elu(float x)   { return x > 0.f ? x : expm1f(x); }

// ---------------- CSR build ----------------
__global__ void k_init_counts() {
    int i = blockIdx.x * blockDim.x + threadIdx.x;
    if (i < NN) { g_cnt[i] = 0; g_cur[i] = 0; }
}

__global__ void k_count(const int* ei, int E0) {
    int e = blockIdx.x * blockDim.x + threadIdx.x;
    if (e >= E0 + NN) return;
    int s, d; get_edge(ei, E0, e, s, d);
    if ((unsigned)s >= NN || (unsigned)d >= NN) return;   // defensive
    atomicAdd(&g_cnt[d], 1);
}

// single-block scan over 10000 counts -> exclusive offsets
__global__ void k_scan() {
    __shared__ int part[1024];
    const int CH = 10;                 // 1024*10 >= 10000
    int tid = threadIdx.x;
    int local[CH];
    int s = 0;
    #pragma unroll
    for (int i = 0; i < CH; i++) {
        int idx = tid * CH + i;
        int v = (idx < NN) ? g_cnt[idx] : 0;
        local[i] = s; s += v;
    }
    part[tid] = s;
    __syncthreads();
    for (int o = 1; o < 1024; o <<= 1) {
        int v = (tid >= o) ? part[tid - o] : 0;
        __syncthreads();
        part[tid] += v;
        __syncthreads();
    }
    int pre = tid ? part[tid - 1] : 0;
    #pragma unroll
    for (int i = 0; i < CH; i++) {
        int idx = tid * CH + i;
        if (idx < NN) g_off[idx] = pre + local[i];
    }
    if (tid == 1023) g_off[NN] = part[1023];
}

__global__ void k_scatter(const int* ei, int E0) {
    int e = blockIdx.x * blockDim.x + threadIdx.x;
    if (e >= E0 + NN) return;
    int s, d; get_edge(ei, E0, e, s, d);
    if ((unsigned)s >= NN || (unsigned)d >= NN) return;   // defensive
    int pos = atomicAdd(&g_cur[d], 1);
    g_csr_src[g_off[d] + pos] = s;
}

// ---------------- SGEMM: C[M,N] = A[M,K] @ B[K,N] ----------------
// dst selector: 0 -> g_xl1, 1 -> g_xl2. A selector: 0 -> external, 1 -> g_h1.
__global__ void k_sgemm(const float* __restrict__ Aext, const float* __restrict__ B,
                        int M, int N, int K, int a_sel, int c_sel) {
    const float* A = a_sel ? g_h1 : Aext;
    float* C = c_sel ? g_xl2 : g_xl1;

    __shared__ float As[16][64];   // As[k][m]
    __shared__ float Bs[16][64];   // Bs[k][n]
    int brow = blockIdx.y * 64;
    int bcol = blockIdx.x * 64;
    int tid = threadIdx.x;
    int tx = tid & 15, ty = tid >> 4;

    float acc[4][4] = {};

    for (int k0 = 0; k0 < K; k0 += 16) {
        {
            int m  = tid >> 2;              // 0..63
            int kk = (tid & 3) * 4;         // 0,4,8,12
            int row = brow + m;
            float4 v = make_float4(0.f, 0.f, 0.f, 0.f);
            if (row < M) v = *(const float4*)(A + (size_t)row * K + k0 + kk);
            As[kk + 0][m] = v.x; As[kk + 1][m] = v.y;
            As[kk + 2][m] = v.z; As[kk + 3][m] = v.w;
        }
        {
            int kk  = tid >> 4;             // 0..15
            int col = (tid & 15) * 4;
            float4 v = *(const float4*)(B + (size_t)(k0 + kk) * N + bcol + col);
            Bs[kk][col + 0] = v.x; Bs[kk][col + 1] = v.y;
            Bs[kk][col + 2] = v.z; Bs[kk][col + 3] = v.w;
        }
        __syncthreads();
        #pragma unroll
        for (int kk = 0; kk < 16; kk++) {
            float a[4], b[4];
            #pragma unroll
            for (int i = 0; i < 4; i++) a[i] = As[kk][ty * 4 + i];
            #pragma unroll
            for (int j = 0; j < 4; j++) b[j] = Bs[kk][tx * 4 + j];
            #pragma unroll
            for (int i = 0; i < 4; i++)
                #pragma unroll
                for (int j = 0; j < 4; j++)
                    acc[i][j] += a[i] * b[j];
        }
        __syncthreads();
    }
    #pragma unroll
    for (int i = 0; i < 4; i++) {
        int row = brow + ty * 4 + i;
        if (row >= M) continue;
        float4 v = make_float4(acc[i][0], acc[i][1], acc[i][2], acc[i][3]);
        *(float4*)(C + (size_t)row * N + bcol + tx * 4) = v;
    }
}

// ---------------- alpha dot products ----------------
__global__ void k_alpha1(const float* __restrict__ a_src,
                         const float* __restrict__ a_dst) {
    int n = blockIdx.x;
    int h = threadIdx.x >> 5;
    int lane = threadIdx.x & 31;
    const float4 v  = *(const float4*)(g_xl1 + (size_t)n * 1024 + h * 128 + lane * 4);
    const float4 as = *(const float4*)(a_src + h * 128 + lane * 4);
    const float4 ad = *(const float4*)(a_dst + h * 128 + lane * 4);
    float s = v.x * as.x + v.y * as.y + v.z * as.z + v.w * as.w;
    float d = v.x * ad.x + v.y * ad.y + v.z * ad.z + v.w * ad.w;
    for (int o = 16; o; o >>= 1) {
        s += __shfl_xor_sync(0xffffffffu, s, o);
        d += __shfl_xor_sync(0xffffffffu, d, o);
    }
    if (lane == 0) { g_as1[n * 8 + h] = s; g_ad1[n * 8 + h] = d; }
}

__global__ void k_alpha2(const float* __restrict__ a_src,
                         const float* __restrict__ a_dst) {
    int n = blockIdx.x * (blockDim.x >> 5) + (threadIdx.x >> 5);
    if (n >= NN) return;
    int lane = threadIdx.x & 31;
    const float4 v  = *(const float4*)(g_xl2 + (size_t)n * 128 + lane * 4);
    const float4 as = *(const float4*)(a_src + lane * 4);
    const float4 ad = *(const float4*)(a_dst + lane * 4);
    float s = v.x * as.x + v.y * as.y + v.z * as.z + v.w * as.w;
    float d = v.x * ad.x + v.y * ad.y + v.z * ad.z + v.w * ad.w;
    for (int o = 16; o; o >>= 1) {
        s += __shfl_xor_sync(0xffffffffu, s, o);
        d += __shfl_xor_sync(0xffffffffu, d, o);
    }
    if (lane == 0) { g_as2[n] = s; g_ad2[n] = d; }
}

// ---------------- fused GAT gather (softmax + aggregate + bias + ELU) ----------
// layer1: 1 block (256 thr) per dst node; warp h handles head h; lane owns 4 ch.
__global__ void k_gather1(const float* __restrict__ bias) {
    int n = blockIdx.x;
    int h = threadIdx.x >> 5;
    int lane = threadIdx.x & 31;
    int beg = g_off[n], end = g_off[n + 1];
    float adv = g_ad1[n * 8 + h];

    float m = -INFINITY;
    for (int i = beg + lane; i < end; i += 32) {
        int s = g_csr_src[i];
        m = fmaxf(m, lrelu(g_as1[s * 8 + h] + adv));
    }
    for (int o = 16; o; o >>= 1) m = fmaxf(m, __shfl_xor_sync(0xffffffffu, m, o));

    float4 acc = make_float4(0.f, 0.f, 0.f, 0.f);
    float denom = 0.f;
    const float* xh = g_xl1 + h * 128 + lane * 4;
    for (int i = beg; i < end; i++) {
        int s = g_csr_src[i];
        float e = lrelu(g_as1[s * 8 + h] + adv);
        float w = __expf(e - m);
        denom += w;
        float4 v = *(const float4*)(xh + (size_t)s * 1024);
        acc.x += w * v.x; acc.y += w * v.y; acc.z += w * v.z; acc.w += w * v.w;
    }
    float inv = 1.f / (denom + 1e-16f);
    int c = h * 128 + lane * 4;
    float4 b = *(const float4*)(bias + c);
    float4 o;
    o.x = elu(acc.x * inv + b.x);
    o.y = elu(acc.y * inv + b.y);
    o.z = elu(acc.z * inv + b.z);
    o.w = elu(acc.w * inv + b.w);
    *(float4*)(g_h1 + (size_t)n * 1024 + c) = o;
}

// layer2: warp per dst node, single head, C=128.
__global__ void k_gather2(const float* __restrict__ bias) {
    int n = blockIdx.x * (blockDim.x >> 5) + (threadIdx.x >> 5);
    if (n >= NN) return;
    int lane = threadIdx.x & 31;
    int beg = g_off[n], end = g_off[n + 1];
    float adv = g_ad2[n];

    float m = -INFINITY;
    for (int i = beg + lane; i < end; i += 32)
        m = fmaxf(m, lrelu(g_as2[g_csr_src[i]] + adv));
    for (int o = 16; o; o >>= 1) m = fmaxf(m, __shfl_xor_sync(0xffffffffu, m, o));

    float4 acc = make_float4(0.f, 0.f, 0.f, 0.f);
    float denom = 0.f;
    for (int i = beg; i < end; i++) {
        int s = g_csr_src[i];
        float w = __expf(lrelu(g_as2[s] + adv) - m);
        denom += w;
        float4 v = *(const float4*)(g_xl2 + (size_t)s * 128 + lane * 4);
        acc.x += w * v.x; acc.y += w * v.y; acc.z += w * v.z; acc.w += w * v.w;
    }
    float inv = 1.f / (denom + 1e-16f);
    float4 b = *(const float4*)(bias + lane * 4);
    float4 o;
    o.x = elu(acc.x * inv + b.x);
    o.y = elu(acc.y * inv + b.y);
    o.z = elu(acc.z * inv + b.z);
    o.w = elu(acc.w * inv + b.w);
    *(float4*)(g_h2 + (size_t)n * 128 + lane * 4) = o;
}

// ---------------- global mean pool (batch int32, sorted) ----------------
__global__ void k_pool(const int* __restrict__ batch) {
    int g = blockIdx.x;            // 64 blocks, 128 threads
    __shared__ int s_lo, s_hi;
    if (threadIdx.x == 0) {
        int lo = 0, hi = NN;
        while (lo < hi) { int mid = (lo + hi) >> 1; if (batch[mid] < g) lo = mid + 1; else hi = mid; }
        s_lo = lo;
        lo = 0; hi = NN;
        while (lo < hi) { int mid = (lo + hi) >> 1; if (batch[mid] < g + 1) lo = mid + 1; else hi = mid; }
        s_hi = lo;
    }
    __syncthreads();
    int lo = s_lo, hi = s_hi;
    int c = threadIdx.x;
    float acc = 0.f;
    for (int n = lo; n < hi; n++) acc += g_h2[(size_t)n * 128 + c];
    float cnt = (float)(hi - lo);
    g_pooled[g * 128 + c] = acc / fmaxf(cnt, 1.f);
}

// ---------------- final MLP: relu(pooled@W + b) @ w2 + b2 ----------------
__global__ void k_mlp(const float* __restrict__ lin1_w, const float* __restrict__ lin1_b,
                      const float* __restrict__ lin2_w, const float* __restrict__ lin2_b,
                      float* __restrict__ out) {
    int g = blockIdx.x;            // 64 blocks, 128 threads
    int t = threadIdx.x;
    __shared__ float sp[128];
    __shared__ float sz[128];
    sp[t] = g_pooled[g * 128 + t];
    __syncthreads();
    float acc = lin1_b[t];
    #pragma unroll 8
    for (int c = 0; c < 128; c++) acc += sp[c] * lin1_w[c * 128 + t];
    sz[t] = fmaxf(acc, 0.f) * lin2_w[t];
    __syncthreads();
    for (int o = 64; o; o >>= 1) {
        if (t < o) sz[t] += sz[t + o];
        __syncthreads();
    }
    if (t == 0) out[g] = sz[0] + lin2_b[0];
}

// ---------------- launch ----------------
extern "C" void kernel_launch(void* const* d_in, const int* in_sizes, int n_in,
                              void* d_out, int out_size) {
    const float* x      = (const float*)d_in[0];
    const int*   ei     = (const int*)d_in[1];     // int32! (JAX x64 disabled)
    const int*   batch  = (const int*)d_in[2];     // int32!
    const float* W1     = (const float*)d_in[3];
    const float* a_src1 = (const float*)d_in[4];
    const float* a_dst1 = (const float*)d_in[5];
    const float* b1     = (const float*)d_in[6];
    const float* W2     = (const float*)d_in[7];
    const float* a_src2 = (const float*)d_in[8];
    const float* a_dst2 = (const float*)d_in[9];
    const float* b2     = (const float*)d_in[10];
    const float* lin1_w = (const float*)d_in[11];
    const float* lin1_b = (const float*)d_in[12];
    const float* lin2_w = (const float*)d_in[13];
    const float* lin2_b = (const float*)d_in[14];
    float* out = (float*)d_out;

    int E0 = in_sizes[1] / 2;       // 320000
    int E  = E0 + NN;               // 330000

    // CSR build (graph shared by both layers)
    k_init_counts<<<(NN + 255) / 256, 256>>>();
    k_count<<<(E + 255) / 256, 256>>>(ei, E0);
    k_scan<<<1, 1024>>>();
    k_scatter<<<(E + 255) / 256, 256>>>(ei, E0);

    // layer 1: xl1 = x @ W1
    {
        dim3 grid(1024 / 64, (NN + 63) / 64);
        k_sgemm<<<grid, 256>>>(x, W1, NN, 1024, 128, /*a_sel=*/0, /*c_sel=*/0);
    }
    k_alpha1<<<NN, 256>>>(a_src1, a_dst1);
    k_gather1<<<NN, 256>>>(b1);

    // layer 2: xl2 = h1 @ W2
    {
        dim3 grid(128 / 64, (NN + 63) / 64);
        k_sgemm<<<grid, 256>>>(x /*unused*/, W2, NN, 128, 1024, /*a_sel=*/1, /*c_sel=*/1);
    }
    k_alpha2<<<(NN * 32 + 255) / 256, 256>>>(a_src2, a_dst2);
    k_gather2<<<(NN * 32 + 255) / 256, 256>>>(b2);

    // pool + MLP head
    k_pool<<<NG, 128>>>(batch);
    k_mlp<<<NG, 128>>>(lin1_w, lin1_b, lin2_w, lin2_b, out);
}